// round 1
// baseline (speedup 1.0000x reference)
#include <cuda_runtime.h>
#include <math.h>

// Problem: x [128, 1, 512, 512] fp32.
//   pred = softplus(x); m = max over sample; out = (m > 1e-8) ? pred/m : pred.
// softplus is monotone => m = softplus(max(x)), so pass 1 is a plain fmax
// reduction over raw x (cheap ALU), softplus is evaluated once per element.
//
// One CTA per sample (128 CTAs, single wave on 148 SMs). Pass 2 re-reads the
// same 1 MB the CTA just streamed in pass 1 -> L2 hit, so HBM traffic is
// ~read 134 MB + write 134 MB.

#define SAMPLE_ELEMS (512 * 512)   // 262144
#define N4 (SAMPLE_ELEMS / 4)      // 65536 float4 per sample
#define THREADS 1024
#define EPS 1e-8f

__device__ __forceinline__ float softplus_f(float x) {
    // Stable: max(x,0) + log1p(exp(-|x|)), matches jnp.logaddexp(x, 0).
    return fmaxf(x, 0.0f) + log1pf(__expf(-fabsf(x)));
}

__global__ __launch_bounds__(THREADS, 1)
void sample_norm_kernel(const float* __restrict__ x, float* __restrict__ out) {
    const int s = blockIdx.x;
    const float4* __restrict__ xin =
        reinterpret_cast<const float4*>(x) + (size_t)s * N4;
    float4* __restrict__ o =
        reinterpret_cast<float4*>(out) + (size_t)s * N4;

    const int tid = threadIdx.x;

    // ---------- Pass 1: per-sample max of raw x ----------
    float m = -INFINITY;
    #pragma unroll 8
    for (int i = tid; i < N4; i += THREADS) {
        float4 v = xin[i];
        m = fmaxf(m, fmaxf(fmaxf(v.x, v.y), fmaxf(v.z, v.w)));
    }

    __shared__ float red[32];
    __shared__ float s_scale;

    // warp reduce
    #pragma unroll
    for (int off = 16; off; off >>= 1)
        m = fmaxf(m, __shfl_xor_sync(0xFFFFFFFFu, m, off));
    if ((tid & 31) == 0) red[tid >> 5] = m;
    __syncthreads();

    if (tid < 32) {
        float v = red[tid];   // exactly 32 warps at 1024 threads
        #pragma unroll
        for (int off = 16; off; off >>= 1)
            v = fmaxf(v, __shfl_xor_sync(0xFFFFFFFFu, v, off));
        if (tid == 0) {
            float sm = softplus_f(v);           // = max(softplus(x)) by monotonicity
            s_scale = (sm > EPS) ? (1.0f / sm) : 1.0f;
        }
    }
    __syncthreads();

    const float scale = s_scale;

    // ---------- Pass 2: softplus * scale (re-read hits L2) ----------
    #pragma unroll 4
    for (int i = tid; i < N4; i += THREADS) {
        float4 v = xin[i];
        float4 r;
        r.x = softplus_f(v.x) * scale;
        r.y = softplus_f(v.y) * scale;
        r.z = softplus_f(v.z) * scale;
        r.w = softplus_f(v.w) * scale;
        o[i] = r;
    }
}

extern "C" void kernel_launch(void* const* d_in, const int* in_sizes, int n_in,
                              void* d_out, int out_size) {
    const float* x = (const float*)d_in[0];
    float* out = (float*)d_out;
    // in_sizes[0] = 128*512*512; one block per sample.
    int samples = in_sizes[0] / SAMPLE_ELEMS;
    sample_norm_kernel<<<samples, THREADS>>>(x, out);
}

// round 2
// speedup vs baseline: 1.0059x; 1.0059x over previous
#include <cuda_runtime.h>
#include <math.h>

// x [128, 1, 512, 512] fp32.
//   pred = softplus(x); m = max over sample; out = (m > 1e-8) ? pred/m : pred.
// softplus monotone => m = softplus(max(x)).
//
// R2 change vs R1: cache-policy control. R1 measured 355 MB DRAM traffic
// (vs 268 MB ideal) because pass-2 re-reads partially missed L2 — the 134 MB
// input is at L2 capacity (126 MB) and pass-2 output writes were evicting it.
// Now: pass-1 loads default (retain in L2), pass-2 loads __ldcs (evict-first,
// last use), pass-2 stores __stcs (streaming, don't pollute L2).

#define SAMPLE_ELEMS (512 * 512)   // 262144
#define N4 (SAMPLE_ELEMS / 4)      // 65536 float4 per sample
#define THREADS 1024
#define EPS 1e-8f

__device__ __forceinline__ float softplus_f(float x) {
    // Stable: max(x,0) + log1p(exp(-|x|)), matches jnp.logaddexp(x, 0).
    return fmaxf(x, 0.0f) + log1pf(__expf(-fabsf(x)));
}

__global__ __launch_bounds__(THREADS, 1)
void sample_norm_kernel(const float* __restrict__ x, float* __restrict__ out) {
    const int s = blockIdx.x;
    const float4* __restrict__ xin =
        reinterpret_cast<const float4*>(x) + (size_t)s * N4;
    float4* __restrict__ o =
        reinterpret_cast<float4*>(out) + (size_t)s * N4;

    const int tid = threadIdx.x;

    // ---------- Pass 1: per-sample max of raw x (default policy: keep in L2) ----------
    // 4 independent accumulators to break the FMNMX dependency chain.
    float m0 = -INFINITY, m1 = -INFINITY, m2 = -INFINITY, m3 = -INFINITY;
    #pragma unroll 4
    for (int i = tid; i < N4; i += 4 * THREADS) {
        float4 a = xin[i];
        float4 b = xin[i + THREADS];
        float4 c = xin[i + 2 * THREADS];
        float4 d = xin[i + 3 * THREADS];
        m0 = fmaxf(m0, fmaxf(fmaxf(a.x, a.y), fmaxf(a.z, a.w)));
        m1 = fmaxf(m1, fmaxf(fmaxf(b.x, b.y), fmaxf(b.z, b.w)));
        m2 = fmaxf(m2, fmaxf(fmaxf(c.x, c.y), fmaxf(c.z, c.w)));
        m3 = fmaxf(m3, fmaxf(fmaxf(d.x, d.y), fmaxf(d.z, d.w)));
    }
    float m = fmaxf(fmaxf(m0, m1), fmaxf(m2, m3));

    __shared__ float red[32];
    __shared__ float s_scale;

    #pragma unroll
    for (int off = 16; off; off >>= 1)
        m = fmaxf(m, __shfl_xor_sync(0xFFFFFFFFu, m, off));
    if ((tid & 31) == 0) red[tid >> 5] = m;
    __syncthreads();

    if (tid < 32) {
        float v = red[tid];   // exactly 32 warps at 1024 threads
        #pragma unroll
        for (int off = 16; off; off >>= 1)
            v = fmaxf(v, __shfl_xor_sync(0xFFFFFFFFu, v, off));
        if (tid == 0) {
            float sm = softplus_f(v);           // = max(softplus(x)) by monotonicity
            s_scale = (sm > EPS) ? (1.0f / sm) : 1.0f;
        }
    }
    __syncthreads();

    const float scale = s_scale;

    // ---------- Pass 2: softplus * scale ----------
    // Loads: streaming (last use).  Stores: streaming (don't evict input in L2).
    #pragma unroll 2
    for (int i = tid; i < N4; i += 2 * THREADS) {
        float4 a = __ldcs(&xin[i]);
        float4 b = __ldcs(&xin[i + THREADS]);
        float4 ra, rb;
        ra.x = softplus_f(a.x) * scale;
        ra.y = softplus_f(a.y) * scale;
        ra.z = softplus_f(a.z) * scale;
        ra.w = softplus_f(a.w) * scale;
        rb.x = softplus_f(b.x) * scale;
        rb.y = softplus_f(b.y) * scale;
        rb.z = softplus_f(b.z) * scale;
        rb.w = softplus_f(b.w) * scale;
        __stcs(&o[i], ra);
        __stcs(&o[i + THREADS], rb);
    }
}

extern "C" void kernel_launch(void* const* d_in, const int* in_sizes, int n_in,
                              void* d_out, int out_size) {
    const float* x = (const float*)d_in[0];
    float* out = (float*)d_out;
    int samples = in_sizes[0] / SAMPLE_ELEMS;   // 128 blocks, one per sample
    sample_norm_kernel<<<samples, THREADS>>>(x, out);
}

// round 3
// speedup vs baseline: 1.0343x; 1.0282x over previous
#include <cuda_runtime.h>
#include <math.h>

// x [128, 1, 512, 512] fp32.
//   pred = softplus(x); m = max over sample; out = (m > 1e-8) ? pred/m : pred.
// softplus monotone => m = softplus(max(x)).
//
// R3: replace the single-CTA-per-sample two-phase kernel (grid=128, 20 idle
// SMs, read phase and write phase serialized by the per-CTA barrier) with a
// 3-kernel graph:
//   K0: reset per-sample max scratch (128 slots)
//   K1: per-sample max via 32 CTAs/sample + atomicMax on ordered-uint floats
//   K2: out = softplus(x) * scale(sample); input re-read hits L2 (resident
//       from K1), streaming loads/stores protect residency.

#define SAMPLES 128
#define SAMPLE_ELEMS (512 * 512)        // 262144
#define SAMPLE_N4 (SAMPLE_ELEMS / 4)    // 65536 float4
#define CHUNKS 32                       // CTAs per sample
#define CHUNK_N4 (SAMPLE_N4 / CHUNKS)   // 2048 float4 per CTA
#define THREADS 256                     // 8 float4 per thread per pass
#define EPS 1e-8f

__device__ unsigned g_sample_max[SAMPLES];

__device__ __forceinline__ unsigned ord_encode(float f) {
    unsigned u = __float_as_uint(f);
    return (u >> 31) ? ~u : (u | 0x80000000u);   // monotone map float -> uint
}
__device__ __forceinline__ float ord_decode(unsigned u) {
    return __uint_as_float((u >> 31) ? (u ^ 0x80000000u) : ~u);
}

__device__ __forceinline__ float softplus_f(float x) {
    // Stable: max(x,0) + log1p(exp(-|x|)), matches jnp.logaddexp(x, 0).
    return fmaxf(x, 0.0f) + log1pf(__expf(-fabsf(x)));
}

// ---------- K0: reset scratch ----------
__global__ void reset_kernel() {
    g_sample_max[threadIdx.x] = 0u;   // 0 < ord_encode(-inf): always overwritten
}

// ---------- K1: per-sample max ----------
__global__ __launch_bounds__(THREADS)
void max_kernel(const float* __restrict__ x) {
    const int sample = blockIdx.x / CHUNKS;
    const int chunk  = blockIdx.x % CHUNKS;
    const float4* __restrict__ xin = reinterpret_cast<const float4*>(x)
        + (size_t)sample * SAMPLE_N4 + (size_t)chunk * CHUNK_N4;
    const int tid = threadIdx.x;

    // 8 float4 per thread, 4 independent accumulators
    float m0 = -INFINITY, m1 = -INFINITY, m2 = -INFINITY, m3 = -INFINITY;
    #pragma unroll
    for (int it = 0; it < 2; it++) {
        int base = it * 4 * THREADS + tid;
        float4 a = xin[base];
        float4 b = xin[base + THREADS];
        float4 c = xin[base + 2 * THREADS];
        float4 d = xin[base + 3 * THREADS];
        m0 = fmaxf(m0, fmaxf(fmaxf(a.x, a.y), fmaxf(a.z, a.w)));
        m1 = fmaxf(m1, fmaxf(fmaxf(b.x, b.y), fmaxf(b.z, b.w)));
        m2 = fmaxf(m2, fmaxf(fmaxf(c.x, c.y), fmaxf(c.z, c.w)));
        m3 = fmaxf(m3, fmaxf(fmaxf(d.x, d.y), fmaxf(d.z, d.w)));
    }
    float m = fmaxf(fmaxf(m0, m1), fmaxf(m2, m3));

    #pragma unroll
    for (int off = 16; off; off >>= 1)
        m = fmaxf(m, __shfl_xor_sync(0xFFFFFFFFu, m, off));

    __shared__ float red[THREADS / 32];
    if ((tid & 31) == 0) red[tid >> 5] = m;
    __syncthreads();
    if (tid < (THREADS / 32)) {
        float v = red[tid];
        #pragma unroll
        for (int off = (THREADS / 64); off; off >>= 1)
            v = fmaxf(v, __shfl_xor_sync(0xFFFFFFFFu, v, off));
        if (tid == 0)
            atomicMax(&g_sample_max[sample], ord_encode(v));
    }
}

// ---------- K2: normalize ----------
__global__ __launch_bounds__(THREADS)
void norm_kernel(const float* __restrict__ x, float* __restrict__ out) {
    const int sample = blockIdx.x / CHUNKS;
    const int chunk  = blockIdx.x % CHUNKS;
    const size_t off4 = (size_t)sample * SAMPLE_N4 + (size_t)chunk * CHUNK_N4;
    const float4* __restrict__ xin = reinterpret_cast<const float4*>(x) + off4;
    float4* __restrict__ o = reinterpret_cast<float4*>(out) + off4;
    const int tid = threadIdx.x;

    __shared__ float s_scale;
    if (tid == 0) {
        float mx = ord_decode(g_sample_max[sample]);
        float sm = softplus_f(mx);          // = max(softplus(x)) by monotonicity
        s_scale = (sm > EPS) ? (1.0f / sm) : 1.0f;
    }
    __syncthreads();
    const float scale = s_scale;

    #pragma unroll
    for (int it = 0; it < 2; it++) {
        int base = it * 4 * THREADS + tid;
        float4 a = __ldcs(&xin[base]);
        float4 b = __ldcs(&xin[base + THREADS]);
        float4 c = __ldcs(&xin[base + 2 * THREADS]);
        float4 d = __ldcs(&xin[base + 3 * THREADS]);
        float4 ra, rb, rc, rd;
        ra.x = softplus_f(a.x) * scale; ra.y = softplus_f(a.y) * scale;
        ra.z = softplus_f(a.z) * scale; ra.w = softplus_f(a.w) * scale;
        rb.x = softplus_f(b.x) * scale; rb.y = softplus_f(b.y) * scale;
        rb.z = softplus_f(b.z) * scale; rb.w = softplus_f(b.w) * scale;
        rc.x = softplus_f(c.x) * scale; rc.y = softplus_f(c.y) * scale;
        rc.z = softplus_f(c.z) * scale; rc.w = softplus_f(c.w) * scale;
        rd.x = softplus_f(d.x) * scale; rd.y = softplus_f(d.y) * scale;
        rd.z = softplus_f(d.z) * scale; rd.w = softplus_f(d.w) * scale;
        __stcs(&o[base], ra);
        __stcs(&o[base + THREADS], rb);
        __stcs(&o[base + 2 * THREADS], rc);
        __stcs(&o[base + 3 * THREADS], rd);
    }
}

extern "C" void kernel_launch(void* const* d_in, const int* in_sizes, int n_in,
                              void* d_out, int out_size) {
    const float* x = (const float*)d_in[0];
    float* out = (float*)d_out;
    reset_kernel<<<1, SAMPLES>>>();
    max_kernel<<<SAMPLES * CHUNKS, THREADS>>>(x);
    norm_kernel<<<SAMPLES * CHUNKS, THREADS>>>(x, out);
}